// round 1
// baseline (speedup 1.0000x reference)
#include <cuda_runtime.h>
#include <cstdint>
#include <cstddef>

// ---------------- problem constants (compile-time) ----------------
#define T_TOKENS   8192
#define DM         2048          // D_MODEL
#define DH         8192          // D_HIDDEN
#define NEXP       8
#define TOPK       2
#define CAP        2560          // ceil(16384/8*1.25)
#define NITEMS     (T_TOKENS*TOPK)

// ---------------- device scratch (static, zero-initialized) -------
__device__ float g_buf [(size_t)NEXP*CAP*DM];     // 160 MB dispatch buffers
__device__ float g_h   [(size_t)NEXP*CAP*DH];     // 640 MB hidden
__device__ float g_oute[(size_t)NEXP*CAP*DM];     // 160 MB expert outputs
__device__ int   g_item_e  [NITEMS];
__device__ float g_item_w  [NITEMS];
__device__ int   g_item_pos[NITEMS];
__device__ int   g_count   [NEXP];

// ---------------- 1) gating: logits, softmax, top-2, renorm -------
__global__ void gating_kernel(const float* __restrict__ x,
                              const float* __restrict__ gw) {
    int t = blockIdx.x;
    const float* xt = x + (size_t)t * DM;
    float acc[NEXP];
#pragma unroll
    for (int e = 0; e < NEXP; e++) acc[e] = 0.f;
    for (int d = threadIdx.x; d < DM; d += blockDim.x) {
        float xv = xt[d];
        const float* g = gw + (size_t)d * NEXP;
#pragma unroll
        for (int e = 0; e < NEXP; e++) acc[e] += xv * g[e];
    }
    __shared__ float red[NEXP][128];
#pragma unroll
    for (int e = 0; e < NEXP; e++) red[e][threadIdx.x] = acc[e];
    __syncthreads();
    for (int s = 64; s > 0; s >>= 1) {
        if (threadIdx.x < s) {
#pragma unroll
            for (int e = 0; e < NEXP; e++)
                red[e][threadIdx.x] += red[e][threadIdx.x + s];
        }
        __syncthreads();
    }
    if (threadIdx.x == 0) {
        float l[NEXP];
#pragma unroll
        for (int e = 0; e < NEXP; e++) l[e] = red[e][0];
        float m = l[0];
#pragma unroll
        for (int e = 1; e < NEXP; e++) m = fmaxf(m, l[e]);
        float p[NEXP]; float Z = 0.f;
#pragma unroll
        for (int e = 0; e < NEXP; e++) { p[e] = __expf(l[e] - m); Z += p[e]; }
        // top-2 (strictly-greater => lowest index wins ties, matches lax.top_k)
        int i0 = 0;
#pragma unroll
        for (int e = 1; e < NEXP; e++) if (p[e] > p[i0]) i0 = e;
        int i1 = (i0 == 0) ? 1 : 0;
#pragma unroll
        for (int e = 0; e < NEXP; e++) if (e != i0 && p[e] > p[i1]) i1 = e;
        float w0 = p[i0] / Z, w1 = p[i1] / Z;
        float s = w0 + w1 + 1e-8f;
        g_item_e[2*t]   = i0;  g_item_e[2*t+1] = i1;
        g_item_w[2*t]   = w0 / s;
        g_item_w[2*t+1] = w1 / s;
    }
}

// ---------------- 2) serial-order positions (single block) --------
// Exact flat-order cumsum: item i = t*2+k. 256 threads x 64 items each.
__global__ void position_kernel() {
    __shared__ int cnt[256][NEXP];
    int tid = threadIdx.x;
    int base = tid * (NITEMS / 256);   // 64 items per thread
    int local[NEXP];
#pragma unroll
    for (int e = 0; e < NEXP; e++) local[e] = 0;
    for (int i = 0; i < NITEMS/256; i++) local[g_item_e[base + i]]++;
#pragma unroll
    for (int e = 0; e < NEXP; e++) cnt[tid][e] = local[e];
    __syncthreads();
    if (tid < NEXP) {
        int run = 0;
        for (int j = 0; j < 256; j++) { int c = cnt[j][tid]; cnt[j][tid] = run; run += c; }
        g_count[tid] = run < CAP ? run : CAP;   // kept rows per expert
    }
    __syncthreads();
    int run[NEXP];
#pragma unroll
    for (int e = 0; e < NEXP; e++) run[e] = cnt[tid][e];
    for (int i = 0; i < NITEMS/256; i++) {
        int e = g_item_e[base + i];
        g_item_pos[base + i] = run[e]++;
    }
}

// ---------------- 3) dispatch: copy x rows into expert buffers ----
__global__ void dispatch_kernel(const float* __restrict__ x) {
    int i = blockIdx.x;
    int pos = g_item_pos[i];
    if (pos >= CAP) return;                     // dropped
    int e = g_item_e[i];
    int t = i >> 1;
    const float4* src = (const float4*)(x + (size_t)t * DM);
    float4* dst = (float4*)(g_buf + ((size_t)e * CAP + pos) * DM);
    for (int j = threadIdx.x; j < DM/4; j += blockDim.x) dst[j] = src[j];
}

// ---------------- 4) batched SGEMM: C = act(A@B + bias) -----------
// A:[E][M][K] row-major, B:[E][K][N] row-major, bias:[E][N], C:[E][M][N]
// 128x128x16 tiles, 256 threads, 8x8 per thread, staged pipeline.
template <bool RELU, bool SKIP_BY_COUNT>
__global__ void __launch_bounds__(256, 2)
gemm_kernel(const float* __restrict__ A, const float* __restrict__ B,
            const float* __restrict__ bias, float* __restrict__ C,
            int M, int N, int K) {
    int e  = blockIdx.z;
    int bm = blockIdx.y * 128;
    int bn = blockIdx.x * 128;
    if (SKIP_BY_COUNT && bm >= g_count[e]) return;   // all-zero rows, never gathered

    A    += (size_t)e * M * K;
    B    += (size_t)e * K * N;
    bias += (size_t)e * N;
    C    += (size_t)e * M * N;

    __shared__ float As[16][128];   // transposed: As[k][m]
    __shared__ float Bs[16][128];   // Bs[k][n]

    int tid = threadIdx.x;
    int tx = tid & 15;              // n
    int ty = tid >> 4;              // m

    // load assignments
    int rA0 = tid >> 2;             // 0..63
    int kqA = (tid & 3) * 4;        // 0,4,8,12
    int rB0 = tid >> 5;             // 0..7
    int cB  = (tid & 31) * 4;       // 0..124

    const float* Aping0 = A + (size_t)(bm + rA0)      * K + kqA;
    const float* Aping1 = A + (size_t)(bm + rA0 + 64) * K + kqA;
    const float* Bping0 = B + (size_t)rB0       * N + bn + cB;
    const float* Bping1 = B + (size_t)(rB0 + 8) * N + bn + cB;

    float acc[8][8];
#pragma unroll
    for (int i = 0; i < 8; i++)
#pragma unroll
        for (int j = 0; j < 8; j++) acc[i][j] = 0.f;

    float4 sA0 = *(const float4*)(Aping0);
    float4 sA1 = *(const float4*)(Aping1);
    float4 sB0 = *(const float4*)(Bping0);
    float4 sB1 = *(const float4*)(Bping1);

    for (int k0 = 0; k0 < K; k0 += 16) {
        // commit staged tile to smem
        As[kqA+0][rA0] = sA0.x; As[kqA+1][rA0] = sA0.y;
        As[kqA+2][rA0] = sA0.z; As[kqA+3][rA0] = sA0.w;
        As[kqA+0][rA0+64] = sA1.x; As[kqA+1][rA0+64] = sA1.y;
        As[kqA+2][rA0+64] = sA1.z; As[kqA+3][rA0+64] = sA1.w;
        *(float4*)&Bs[rB0][cB]     = sB0;
        *(float4*)&Bs[rB0 + 8][cB] = sB1;
        __syncthreads();

        if (k0 + 16 < K) {   // prefetch next tile while computing
            sA0 = *(const float4*)(Aping0 + k0 + 16);
            sA1 = *(const float4*)(Aping1 + k0 + 16);
            sB0 = *(const float4*)(Bping0 + (size_t)(k0 + 16) * N);
            sB1 = *(const float4*)(Bping1 + (size_t)(k0 + 16) * N);
        }

#pragma unroll
        for (int kk = 0; kk < 16; kk++) {
            float4 a0 = *(const float4*)&As[kk][ty * 4];
            float4 a1 = *(const float4*)&As[kk][64 + ty * 4];
            float4 b0 = *(const float4*)&Bs[kk][tx * 4];
            float4 b1 = *(const float4*)&Bs[kk][64 + tx * 4];
            float av[8] = {a0.x,a0.y,a0.z,a0.w,a1.x,a1.y,a1.z,a1.w};
            float bv[8] = {b0.x,b0.y,b0.z,b0.w,b1.x,b1.y,b1.z,b1.w};
#pragma unroll
            for (int i = 0; i < 8; i++)
#pragma unroll
                for (int j = 0; j < 8; j++)
                    acc[i][j] += av[i] * bv[j];
        }
        __syncthreads();
    }

    // epilogue: + bias, optional relu
    float4 bi0 = *(const float4*)(bias + bn + tx * 4);
    float4 bi1 = *(const float4*)(bias + bn + 64 + tx * 4);
    float bb[8] = {bi0.x,bi0.y,bi0.z,bi0.w,bi1.x,bi1.y,bi1.z,bi1.w};
#pragma unroll
    for (int i = 0; i < 8; i++) {
        int m = bm + ((i < 4) ? (ty * 4 + i) : (64 + ty * 4 + i - 4));
        float out[8];
#pragma unroll
        for (int j = 0; j < 8; j++) {
            float v = acc[i][j] + bb[j];
            out[j] = RELU ? fmaxf(v, 0.f) : v;
        }
        float4 o0 = {out[0], out[1], out[2], out[3]};
        float4 o1 = {out[4], out[5], out[6], out[7]};
        *(float4*)(C + (size_t)m * N + bn + tx * 4)      = o0;
        *(float4*)(C + (size_t)m * N + bn + 64 + tx * 4) = o1;
    }
}

// ---------------- 5) combine: out[t] = sum_k w_k * oute[e,pos] ----
__global__ void combine_kernel(float* __restrict__ out) {
    int t = blockIdx.x;
    int i0 = 2 * t, i1 = 2 * t + 1;
    int e0 = g_item_e[i0], e1 = g_item_e[i1];
    int p0 = g_item_pos[i0], p1 = g_item_pos[i1];
    float w0 = (p0 < CAP) ? g_item_w[i0] : 0.f;
    float w1 = (p1 < CAP) ? g_item_w[i1] : 0.f;
    if (p0 >= CAP) p0 = CAP - 1;
    if (p1 >= CAP) p1 = CAP - 1;
    const float4* s0 = (const float4*)(g_oute + ((size_t)e0 * CAP + p0) * DM);
    const float4* s1 = (const float4*)(g_oute + ((size_t)e1 * CAP + p1) * DM);
    float4* dst = (float4*)(out + (size_t)t * DM);
    for (int j = threadIdx.x; j < DM/4; j += blockDim.x) {
        float4 a = s0[j], b = s1[j];
        float4 r;
        r.x = w0 * a.x + w1 * b.x;
        r.y = w0 * a.y + w1 * b.y;
        r.z = w0 * a.z + w1 * b.z;
        r.w = w0 * a.w + w1 * b.w;
        dst[j] = r;
    }
}

// ---------------- launcher ----------------------------------------
extern "C" void kernel_launch(void* const* d_in, const int* in_sizes, int n_in,
                              void* d_out, int out_size) {
    const float* x  = (const float*)d_in[0];   // [4,2048,2048]
    const float* gw = (const float*)d_in[1];   // [2048,8]
    const float* w1 = (const float*)d_in[2];   // [8,2048,8192]
    const float* b1 = (const float*)d_in[3];   // [8,8192]
    const float* w2 = (const float*)d_in[4];   // [8,8192,2048]
    const float* b2 = (const float*)d_in[5];   // [8,2048]
    float* out = (float*)d_out;

    void *pbuf, *ph, *poute;
    cudaGetSymbolAddress(&pbuf,  g_buf);
    cudaGetSymbolAddress(&ph,    g_h);
    cudaGetSymbolAddress(&poute, g_oute);

    gating_kernel<<<T_TOKENS, 128>>>(x, gw);
    position_kernel<<<1, 256>>>();
    dispatch_kernel<<<NITEMS, 128>>>(x);

    // h = relu(buf @ w1 + b1): M=CAP, N=DH, K=DM
    gemm_kernel<true, true><<<dim3(DH/128, CAP/128, NEXP), 256>>>(
        (const float*)pbuf, w1, b1, (float*)ph, CAP, DH, DM);

    // oute = h @ w2 + b2: M=CAP, N=DM, K=DH
    gemm_kernel<false, true><<<dim3(DM/128, CAP/128, NEXP), 256>>>(
        (const float*)ph, w2, b2, (float*)poute, CAP, DM, DH);

    combine_kernel<<<T_TOKENS, 128>>>(out);
}

// round 3
// speedup vs baseline: 2.1390x; 2.1390x over previous
#include <cuda_runtime.h>
#include <cstdint>
#include <cstddef>

// ---------------- problem constants ----------------
#define T_TOKENS   8192
#define DM         2048
#define DH         8192
#define NEXP       8
#define CAP        2560
#define NITEMS     (T_TOKENS*2)

// ---------------- device scratch (static) ----------
__device__ float g_buf [(size_t)NEXP*CAP*DM];     // dispatched x (tf32-rounded)
__device__ float g_h   [(size_t)NEXP*CAP*DH];     // hidden (tf32-rounded)
__device__ float g_oute[(size_t)NEXP*CAP*DM];     // expert outputs (fp32)
__device__ int   g_item_e  [NITEMS];
__device__ float g_item_w  [NITEMS];
__device__ int   g_item_pos[NITEMS];
__device__ int   g_count   [NEXP];

// ---------------- helpers --------------------------
__device__ __forceinline__ float tf32rn(float x) {
    uint32_t u; asm("cvt.rna.tf32.f32 %0, %1;" : "=r"(u) : "f"(x));
    return __uint_as_float(u);
}
__device__ __forceinline__ uint32_t tf32u(float x) {
    uint32_t u; asm("cvt.rna.tf32.f32 %0, %1;" : "=r"(u) : "f"(x));
    return u;
}
__device__ __forceinline__ uint32_t smem_u32(const void* p) {
    uint32_t a;
    asm("{ .reg .u64 t; cvta.to.shared.u64 t, %1; cvt.u32.u64 %0, t; }" : "=r"(a) : "l"(p));
    return a;
}
__device__ __forceinline__ void cpasync16(uint32_t dst, const void* src) {
    asm volatile("cp.async.cg.shared.global [%0], [%1], 16;" :: "r"(dst), "l"(src));
}
__device__ __forceinline__ void cp_commit() {
    asm volatile("cp.async.commit_group;" ::: "memory");
}
__device__ __forceinline__ void cp_wait1() {
    asm volatile("cp.async.wait_group 1;" ::: "memory");
}
__device__ __forceinline__ void cp_wait0() {
    asm volatile("cp.async.wait_group 0;" ::: "memory");
}
__device__ __forceinline__ void mma_tf32(float* c, const uint32_t* a, const uint32_t* b) {
    asm volatile(
        "mma.sync.aligned.m16n8k8.row.col.f32.tf32.tf32.f32 "
        "{%0,%1,%2,%3}, {%4,%5,%6,%7}, {%8,%9}, {%0,%1,%2,%3};"
        : "+f"(c[0]), "+f"(c[1]), "+f"(c[2]), "+f"(c[3])
        : "r"(a[0]), "r"(a[1]), "r"(a[2]), "r"(a[3]), "r"(b[0]), "r"(b[1]));
}

// ---------------- 1) gating -------------------------
__global__ void gating_kernel(const float* __restrict__ x,
                              const float* __restrict__ gw) {
    int t = blockIdx.x;
    const float* xt = x + (size_t)t * DM;
    float acc[NEXP];
#pragma unroll
    for (int e = 0; e < NEXP; e++) acc[e] = 0.f;
    for (int d = threadIdx.x; d < DM; d += blockDim.x) {
        float xv = xt[d];
        const float* g = gw + (size_t)d * NEXP;
#pragma unroll
        for (int e = 0; e < NEXP; e++) acc[e] += xv * g[e];
    }
    __shared__ float red[NEXP][128];
#pragma unroll
    for (int e = 0; e < NEXP; e++) red[e][threadIdx.x] = acc[e];
    __syncthreads();
    for (int s = 64; s > 0; s >>= 1) {
        if (threadIdx.x < s) {
#pragma unroll
            for (int e = 0; e < NEXP; e++)
                red[e][threadIdx.x] += red[e][threadIdx.x + s];
        }
        __syncthreads();
    }
    if (threadIdx.x == 0) {
        float l[NEXP];
#pragma unroll
        for (int e = 0; e < NEXP; e++) l[e] = red[e][0];
        float m = l[0];
#pragma unroll
        for (int e = 1; e < NEXP; e++) m = fmaxf(m, l[e]);
        float p[NEXP]; float Z = 0.f;
#pragma unroll
        for (int e = 0; e < NEXP; e++) { p[e] = __expf(l[e] - m); Z += p[e]; }
        int i0 = 0;
#pragma unroll
        for (int e = 1; e < NEXP; e++) if (p[e] > p[i0]) i0 = e;
        int i1 = (i0 == 0) ? 1 : 0;
#pragma unroll
        for (int e = 0; e < NEXP; e++) if (e != i0 && p[e] > p[i1]) i1 = e;
        float w0 = p[i0] / Z, w1 = p[i1] / Z;
        float s = w0 + w1 + 1e-8f;
        g_item_e[2*t]   = i0;  g_item_e[2*t+1] = i1;
        g_item_w[2*t]   = w0 / s;
        g_item_w[2*t+1] = w1 / s;
    }
}

// ---------------- 2) serial positions ---------------
__global__ void position_kernel() {
    __shared__ int cnt[256][NEXP];
    int tid = threadIdx.x;
    int base = tid * (NITEMS / 256);
    int local[NEXP];
#pragma unroll
    for (int e = 0; e < NEXP; e++) local[e] = 0;
    for (int i = 0; i < NITEMS/256; i++) local[g_item_e[base + i]]++;
#pragma unroll
    for (int e = 0; e < NEXP; e++) cnt[tid][e] = local[e];
    __syncthreads();
    if (tid < NEXP) {
        int run = 0;
        for (int j = 0; j < 256; j++) { int c = cnt[j][tid]; cnt[j][tid] = run; run += c; }
        g_count[tid] = run < CAP ? run : CAP;
    }
    __syncthreads();
    int run[NEXP];
#pragma unroll
    for (int e = 0; e < NEXP; e++) run[e] = cnt[tid][e];
    for (int i = 0; i < NITEMS/256; i++) {
        int e = g_item_e[base + i];
        g_item_pos[base + i] = run[e]++;
    }
}

// ---------------- 3) dispatch (tf32 round) ----------
__global__ void dispatch_kernel(const float* __restrict__ x) {
    int i = blockIdx.x;
    int pos = g_item_pos[i];
    if (pos >= CAP) return;
    int e = g_item_e[i];
    int t = i >> 1;
    const float4* src = (const float4*)(x + (size_t)t * DM);
    float4* dst = (float4*)(g_buf + ((size_t)e * CAP + pos) * DM);
    for (int j = threadIdx.x; j < DM/4; j += blockDim.x) {
        float4 v = src[j];
        v.x = tf32rn(v.x); v.y = tf32rn(v.y); v.z = tf32rn(v.z); v.w = tf32rn(v.w);
        dst[j] = v;
    }
}

// ---------------- 4) HMMA TF32 GEMM -----------------
// C[e] = act(A[e] @ B[e] + bias[e]);  A:[CAP][K] (tf32 values), B:[K][N] fp32
// CTA 128x128x32, 4 warps of 64x64, 2-stage cp.async double buffer.
// Smem swizzles: A[m][k] at k ^= (m&7)<<2 (16B units x4), B[k][n] at n ^= (k&3)<<3.
#define GSMEM (2*(128*32 + 32*128)*4)   // 64 KB

template<bool RELU, bool CVT>
__global__ void __launch_bounds__(128, 2)
moe_gemm(const float* __restrict__ Aall, const float* __restrict__ Ball,
         const float* __restrict__ biasall, float* __restrict__ Call,
         int N, int K) {
    int e  = blockIdx.z;
    int bm = blockIdx.y * 128;
    int bn = blockIdx.x * 128;
    if (bm >= g_count[e]) return;

    const float* A = Aall + (size_t)e * CAP * K + (size_t)bm * K;
    const float* B = Ball + (size_t)e * K * N + bn;
    const float* bias = biasall + (size_t)e * N + bn;
    float* C = Call + (size_t)e * CAP * N;

    extern __shared__ float smem[];
    uint32_t sbase = smem_u32(smem);

    int tid = threadIdx.x;
    int wid = tid >> 5, lane = tid & 31;
    int gr = lane >> 2, tg = lane & 3;
    int wm = (wid & 1) * 64, wn = (wid >> 1) * 64;

    // staging assignments
    int b_r = tid >> 2;            // B row 0..31
    int b_c = tid & 3;             // B chunk phase
    const float* aRow = A + (size_t)tid * K;           // A row m = tid
    const float* bRow = B + (size_t)b_r * N;

    float acc[4][8][4];
#pragma unroll
    for (int mi = 0; mi < 4; mi++)
#pragma unroll
        for (int ni = 0; ni < 8; ni++)
#pragma unroll
            for (int r = 0; r < 4; r++) acc[mi][ni][r] = 0.f;

    int NB = K / 32;

    // stage loader: buffer buf, k offset kbig*32
    auto stage = [&](int buf, int kbig) {
        uint32_t aDst = sbase + buf * 16384 + tid * 128;          // bytes
        const float* aSrc = aRow + kbig * 32;
#pragma unroll
        for (int c = 0; c < 8; c++)
            cpasync16(aDst + (((uint32_t)(c ^ (tid & 7))) << 4), aSrc + c * 4);
        uint32_t bDst = sbase + 32768 + buf * 16384 + b_r * 512;
        const float* bSrc = bRow + (size_t)kbig * 32 * N;
#pragma unroll
        for (int j = 0; j < 8; j++) {
            int c = b_c + j * 4;
            cpasync16(bDst + (((uint32_t)(c ^ ((b_r & 3) << 1))) << 4), bSrc + c * 4);
        }
    };

    stage(0, 0);
    cp_commit();

    for (int big = 0; big < NB; big++) {
        if (big + 1 < NB) {
            stage((big + 1) & 1, big + 1);
            cp_commit();
            cp_wait1();
        } else {
            cp_wait0();
        }
        __syncthreads();

        const float* sA = smem + (big & 1) * 4096;
        const float* sB = smem + 8192 + (big & 1) * 4096;
#pragma unroll
        for (int kk = 0; kk < 32; kk += 8) {
            uint32_t a[4][4];
#pragma unroll
            for (int mi = 0; mi < 4; mi++) {
                int m0 = wm + mi * 16 + gr;
                int k0 = (kk + tg) ^ (gr << 2);
                int k1 = (kk + tg + 4) ^ (gr << 2);
                a[mi][0] = __float_as_uint(sA[m0 * 32 + k0]);
                a[mi][1] = __float_as_uint(sA[(m0 + 8) * 32 + k0]);
                a[mi][2] = __float_as_uint(sA[m0 * 32 + k1]);
                a[mi][3] = __float_as_uint(sA[(m0 + 8) * 32 + k1]);
            }
            uint32_t b[8][2];
#pragma unroll
            for (int ni = 0; ni < 8; ni++) {
                int n0 = wn + ni * 8 + gr;
                int nsw = n0 ^ (tg << 3);
                b[ni][0] = tf32u(sB[(kk + tg) * 128 + nsw]);
                b[ni][1] = tf32u(sB[(kk + tg + 4) * 128 + nsw]);
            }
#pragma unroll
            for (int mi = 0; mi < 4; mi++)
#pragma unroll
                for (int ni = 0; ni < 8; ni++)
                    mma_tf32(acc[mi][ni], a[mi], b[ni]);
        }
        __syncthreads();
    }

    // epilogue
#pragma unroll
    for (int mi = 0; mi < 4; mi++) {
        int row0 = bm + wm + mi * 16 + gr;
        int row1 = row0 + 8;
#pragma unroll
        for (int ni = 0; ni < 8; ni++) {
            int col = wn + ni * 8 + 2 * tg;
            float2 b2 = *(const float2*)(bias + col);
            float v0 = acc[mi][ni][0] + b2.x;
            float v1 = acc[mi][ni][1] + b2.y;
            float v2 = acc[mi][ni][2] + b2.x;
            float v3 = acc[mi][ni][3] + b2.y;
            if (RELU) {
                v0 = fmaxf(v0, 0.f); v1 = fmaxf(v1, 0.f);
                v2 = fmaxf(v2, 0.f); v3 = fmaxf(v3, 0.f);
            }
            if (CVT) {
                v0 = tf32rn(v0); v1 = tf32rn(v1);
                v2 = tf32rn(v2); v3 = tf32rn(v3);
            }
            float2 o0 = {v0, v1}, o1 = {v2, v3};
            *(float2*)(C + (size_t)row0 * N + bn + col) = o0;
            *(float2*)(C + (size_t)row1 * N + bn + col) = o1;
        }
    }
}

// ---------------- 5) combine ------------------------
__global__ void combine_kernel(float* __restrict__ out) {
    int t = blockIdx.x;
    int i0 = 2 * t, i1 = 2 * t + 1;
    int e0 = g_item_e[i0], e1 = g_item_e[i1];
    int p0 = g_item_pos[i0], p1 = g_item_pos[i1];
    float w0 = (p0 < CAP) ? g_item_w[i0] : 0.f;
    float w1 = (p1 < CAP) ? g_item_w[i1] : 0.f;
    if (p0 >= CAP) p0 = CAP - 1;
    if (p1 >= CAP) p1 = CAP - 1;
    const float4* s0 = (const float4*)(g_oute + ((size_t)e0 * CAP + p0) * DM);
    const float4* s1 = (const float4*)(g_oute + ((size_t)e1 * CAP + p1) * DM);
    float4* dst = (float4*)(out + (size_t)t * DM);
    for (int j = threadIdx.x; j < DM/4; j += blockDim.x) {
        float4 a = s0[j], b = s1[j];
        float4 r;
        r.x = w0 * a.x + w1 * b.x;
        r.y = w0 * a.y + w1 * b.y;
        r.z = w0 * a.z + w1 * b.z;
        r.w = w0 * a.w + w1 * b.w;
        dst[j] = r;
    }
}

// ---------------- launcher --------------------------
extern "C" void kernel_launch(void* const* d_in, const int* in_sizes, int n_in,
                              void* d_out, int out_size) {
    const float* x  = (const float*)d_in[0];
    const float* gw = (const float*)d_in[1];
    const float* w1 = (const float*)d_in[2];
    const float* b1 = (const float*)d_in[3];
    const float* w2 = (const float*)d_in[4];
    const float* b2 = (const float*)d_in[5];
    float* out = (float*)d_out;

    void *pbuf, *ph, *poute;
    cudaGetSymbolAddress(&pbuf,  g_buf);
    cudaGetSymbolAddress(&ph,    g_h);
    cudaGetSymbolAddress(&poute, g_oute);

    cudaFuncSetAttribute(moe_gemm<true,  true >, cudaFuncAttributeMaxDynamicSharedMemorySize, GSMEM);
    cudaFuncSetAttribute(moe_gemm<false, false>, cudaFuncAttributeMaxDynamicSharedMemorySize, GSMEM);

    gating_kernel<<<T_TOKENS, 128>>>(x, gw);
    position_kernel<<<1, 256>>>();
    dispatch_kernel<<<NITEMS, 128>>>(x);

    // h = relu(buf @ w1 + b1): N=DH, K=DM
    moe_gemm<true,  true ><<<dim3(DH/128, CAP/128, NEXP), 128, GSMEM>>>(
        (const float*)pbuf, w1, b1, (float*)ph, DH, DM);
    // oute = h @ w2 + b2: N=DM, K=DH
    moe_gemm<false, false><<<dim3(DM/128, CAP/128, NEXP), 128, GSMEM>>>(
        (const float*)ph, w2, b2, (float*)poute, DM, DH);

    combine_kernel<<<T_TOKENS, 128>>>(out);
}

// round 4
// speedup vs baseline: 2.2163x; 1.0362x over previous
#include <cuda_runtime.h>
#include <cstdint>
#include <cstddef>

// ---------------- problem constants ----------------
#define T_TOKENS   8192
#define DM         2048
#define DH         8192
#define NEXP       8
#define CAP        2560
#define NITEMS     (T_TOKENS*2)

// ---------------- device scratch (static) ----------
__device__ float g_buf [(size_t)NEXP*CAP*DM];     // dispatched x (tf32-rounded)
__device__ float g_h   [(size_t)NEXP*CAP*DH];     // hidden (tf32-rounded)
__device__ float g_oute[(size_t)NEXP*CAP*DM];     // expert outputs (fp32)
__device__ int   g_item_e  [NITEMS];
__device__ float g_item_w  [NITEMS];
__device__ int   g_item_pos[NITEMS];
__device__ int   g_count   [NEXP];

// ---------------- helpers --------------------------
__device__ __forceinline__ float tf32rn(float x) {
    uint32_t u; asm("cvt.rna.tf32.f32 %0, %1;" : "=r"(u) : "f"(x));
    return __uint_as_float(u);
}
__device__ __forceinline__ uint32_t tf32u(float x) {
    uint32_t u; asm("cvt.rna.tf32.f32 %0, %1;" : "=r"(u) : "f"(x));
    return u;
}
__device__ __forceinline__ uint32_t smem_u32(const void* p) {
    uint32_t a;
    asm("{ .reg .u64 t; cvta.to.shared.u64 t, %1; cvt.u32.u64 %0, t; }" : "=r"(a) : "l"(p));
    return a;
}
__device__ __forceinline__ void cpasync16(uint32_t dst, const void* src) {
    asm volatile("cp.async.cg.shared.global [%0], [%1], 16;" :: "r"(dst), "l"(src));
}
__device__ __forceinline__ void cp_commit() {
    asm volatile("cp.async.commit_group;" ::: "memory");
}
__device__ __forceinline__ void cp_wait1() {
    asm volatile("cp.async.wait_group 1;" ::: "memory");
}
__device__ __forceinline__ void cp_wait0() {
    asm volatile("cp.async.wait_group 0;" ::: "memory");
}
__device__ __forceinline__ void mma_tf32(float* c, const uint32_t* a, const uint32_t* b) {
    asm volatile(
        "mma.sync.aligned.m16n8k8.row.col.f32.tf32.tf32.f32 "
        "{%0,%1,%2,%3}, {%4,%5,%6,%7}, {%8,%9}, {%0,%1,%2,%3};"
        : "+f"(c[0]), "+f"(c[1]), "+f"(c[2]), "+f"(c[3])
        : "r"(a[0]), "r"(a[1]), "r"(a[2]), "r"(a[3]), "r"(b[0]), "r"(b[1]));
}

// ---------------- 1) gating -------------------------
__global__ void gating_kernel(const float* __restrict__ x,
                              const float* __restrict__ gw) {
    int t = blockIdx.x;
    const float* xt = x + (size_t)t * DM;
    float acc[NEXP];
#pragma unroll
    for (int e = 0; e < NEXP; e++) acc[e] = 0.f;
    for (int d = threadIdx.x; d < DM; d += blockDim.x) {
        float xv = xt[d];
        const float* g = gw + (size_t)d * NEXP;
#pragma unroll
        for (int e = 0; e < NEXP; e++) acc[e] += xv * g[e];
    }
    __shared__ float red[NEXP][128];
#pragma unroll
    for (int e = 0; e < NEXP; e++) red[e][threadIdx.x] = acc[e];
    __syncthreads();
    for (int s = 64; s > 0; s >>= 1) {
        if (threadIdx.x < s) {
#pragma unroll
            for (int e = 0; e < NEXP; e++)
                red[e][threadIdx.x] += red[e][threadIdx.x + s];
        }
        __syncthreads();
    }
    if (threadIdx.x == 0) {
        float l[NEXP];
#pragma unroll
        for (int e = 0; e < NEXP; e++) l[e] = red[e][0];
        float m = l[0];
#pragma unroll
        for (int e = 1; e < NEXP; e++) m = fmaxf(m, l[e]);
        float p[NEXP]; float Z = 0.f;
#pragma unroll
        for (int e = 0; e < NEXP; e++) { p[e] = __expf(l[e] - m); Z += p[e]; }
        int i0 = 0;
#pragma unroll
        for (int e = 1; e < NEXP; e++) if (p[e] > p[i0]) i0 = e;
        int i1 = (i0 == 0) ? 1 : 0;
#pragma unroll
        for (int e = 0; e < NEXP; e++) if (e != i0 && p[e] > p[i1]) i1 = e;
        float w0 = p[i0] / Z, w1 = p[i1] / Z;
        float s = w0 + w1 + 1e-8f;
        g_item_e[2*t]   = i0;  g_item_e[2*t+1] = i1;
        g_item_w[2*t]   = w0 / s;
        g_item_w[2*t+1] = w1 / s;
    }
}

// ---------------- 2) serial positions ---------------
__global__ void position_kernel() {
    __shared__ int cnt[256][NEXP];
    int tid = threadIdx.x;
    int base = tid * (NITEMS / 256);
    int local[NEXP];
#pragma unroll
    for (int e = 0; e < NEXP; e++) local[e] = 0;
    for (int i = 0; i < NITEMS/256; i++) local[g_item_e[base + i]]++;
#pragma unroll
    for (int e = 0; e < NEXP; e++) cnt[tid][e] = local[e];
    __syncthreads();
    if (tid < NEXP) {
        int run = 0;
        for (int j = 0; j < 256; j++) { int c = cnt[j][tid]; cnt[j][tid] = run; run += c; }
        g_count[tid] = run < CAP ? run : CAP;
    }
    __syncthreads();
    int run[NEXP];
#pragma unroll
    for (int e = 0; e < NEXP; e++) run[e] = cnt[tid][e];
    for (int i = 0; i < NITEMS/256; i++) {
        int e = g_item_e[base + i];
        g_item_pos[base + i] = run[e]++;
    }
}

// ---------------- 3) dispatch (tf32 round) ----------
__global__ void dispatch_kernel(const float* __restrict__ x) {
    int i = blockIdx.x;
    int pos = g_item_pos[i];
    if (pos >= CAP) return;
    int e = g_item_e[i];
    int t = i >> 1;
    const float4* src = (const float4*)(x + (size_t)t * DM);
    float4* dst = (float4*)(g_buf + ((size_t)e * CAP + pos) * DM);
    for (int j = threadIdx.x; j < DM/4; j += blockDim.x) {
        float4 v = src[j];
        v.x = tf32rn(v.x); v.y = tf32rn(v.y); v.z = tf32rn(v.z); v.w = tf32rn(v.w);
        dst[j] = v;
    }
}

// ---------------- 4) HMMA TF32 GEMM -----------------
// C[e] = act(A[e] @ B[e] + bias[e]);  A:[CAP][K] (tf32 values), B:[K][N] fp32
// CTA 128x128x32, 4 warps of 64x64, 3-stage cp.async pipeline,
// ONE __syncthreads per K-iteration (cutlass-style schedule).
#define GSMEM (3*(128*32 + 32*128)*4)   // 96 KB

template<bool RELU, bool CVT>
__global__ void __launch_bounds__(128, 2)
moe_gemm(const float* __restrict__ Aall, const float* __restrict__ Ball,
         const float* __restrict__ biasall, float* __restrict__ Call,
         int N, int K) {
    int e  = blockIdx.z;
    int bm = blockIdx.y * 128;
    int bn = blockIdx.x * 128;
    if (bm >= g_count[e]) return;

    const float* A = Aall + (size_t)e * CAP * K + (size_t)bm * K;
    const float* B = Ball + (size_t)e * K * N + bn;
    const float* bias = biasall + (size_t)e * N + bn;
    float* C = Call + (size_t)e * CAP * N;

    extern __shared__ float smem[];
    uint32_t sbase = smem_u32(smem);

    int tid = threadIdx.x;
    int wid = tid >> 5, lane = tid & 31;
    int gr = lane >> 2, tg = lane & 3;
    int wm = (wid & 1) * 64, wn = (wid >> 1) * 64;

    // staging assignments
    int b_r = tid >> 2;            // B row 0..31
    int b_c = tid & 3;             // B chunk phase
    const float* aRow = A + (size_t)tid * K;           // A row m = tid
    const float* bRow = B + (size_t)b_r * N;

    float acc[4][8][4];
#pragma unroll
    for (int mi = 0; mi < 4; mi++)
#pragma unroll
        for (int ni = 0; ni < 8; ni++)
#pragma unroll
            for (int r = 0; r < 4; r++) acc[mi][ni][r] = 0.f;

    int NB = K / 32;

    // stage loader: buffer buf (0..2), k offset kbig*32
    auto stage = [&](int buf, int kbig) {
        uint32_t aDst = sbase + buf * 16384 + tid * 128;          // bytes
        const float* aSrc = aRow + kbig * 32;
#pragma unroll
        for (int c = 0; c < 8; c++)
            cpasync16(aDst + (((uint32_t)(c ^ (tid & 7))) << 4), aSrc + c * 4);
        uint32_t bDst = sbase + 49152 + buf * 16384 + b_r * 512;
        const float* bSrc = bRow + (size_t)kbig * 32 * N;
#pragma unroll
        for (int j = 0; j < 8; j++) {
            int c = b_c + j * 4;
            cpasync16(bDst + (((uint32_t)(c ^ ((b_r & 3) << 1))) << 4), bSrc + c * 4);
        }
    };

    // prologue: stages 0 and 1 in flight
    stage(0, 0); cp_commit();
    stage(1, 1); cp_commit();

    int buf = 0;
    for (int big = 0; big < NB; big++) {
        // wait for stage 'big' to land
        if (big + 2 < NB) cp_wait1(); else cp_wait0();
        __syncthreads();   // single barrier per iteration

        // issue stage big+2 into the buffer consumed at iter big-1
        if (big + 2 < NB) {
            int nbuf = buf + 2; if (nbuf >= 3) nbuf -= 3;
            stage(nbuf, big + 2);
            cp_commit();
        }

        const float* sA = smem + buf * 4096;
        const float* sB = smem + 12288 + buf * 4096;
#pragma unroll
        for (int kk = 0; kk < 32; kk += 8) {
            uint32_t a[4][4];
#pragma unroll
            for (int mi = 0; mi < 4; mi++) {
                int m0 = wm + mi * 16 + gr;
                int k0 = (kk + tg) ^ (gr << 2);
                int k1 = (kk + tg + 4) ^ (gr << 2);
                a[mi][0] = __float_as_uint(sA[m0 * 32 + k0]);
                a[mi][1] = __float_as_uint(sA[(m0 + 8) * 32 + k0]);
                a[mi][2] = __float_as_uint(sA[m0 * 32 + k1]);
                a[mi][3] = __float_as_uint(sA[(m0 + 8) * 32 + k1]);
            }
            uint32_t b[8][2];
#pragma unroll
            for (int ni = 0; ni < 8; ni++) {
                int n0 = wn + ni * 8 + gr;
                int nsw = n0 ^ (tg << 3);
                b[ni][0] = tf32u(sB[(kk + tg) * 128 + nsw]);
                b[ni][1] = tf32u(sB[(kk + tg + 4) * 128 + nsw]);
            }
#pragma unroll
            for (int mi = 0; mi < 4; mi++)
#pragma unroll
                for (int ni = 0; ni < 8; ni++)
                    mma_tf32(acc[mi][ni], a[mi], b[ni]);
        }

        buf++; if (buf >= 3) buf = 0;
    }

    // epilogue
#pragma unroll
    for (int mi = 0; mi < 4; mi++) {
        int row0 = bm + wm + mi * 16 + gr;
        int row1 = row0 + 8;
#pragma unroll
        for (int ni = 0; ni < 8; ni++) {
            int col = wn + ni * 8 + 2 * tg;
            float2 b2 = *(const float2*)(bias + col);
            float v0 = acc[mi][ni][0] + b2.x;
            float v1 = acc[mi][ni][1] + b2.y;
            float v2 = acc[mi][ni][2] + b2.x;
            float v3 = acc[mi][ni][3] + b2.y;
            if (RELU) {
                v0 = fmaxf(v0, 0.f); v1 = fmaxf(v1, 0.f);
                v2 = fmaxf(v2, 0.f); v3 = fmaxf(v3, 0.f);
            }
            if (CVT) {
                v0 = tf32rn(v0); v1 = tf32rn(v1);
                v2 = tf32rn(v2); v3 = tf32rn(v3);
            }
            float2 o0 = {v0, v1}, o1 = {v2, v3};
            *(float2*)(C + (size_t)row0 * N + bn + col) = o0;
            *(float2*)(C + (size_t)row1 * N + bn + col) = o1;
        }
    }
}

// ---------------- 5) combine ------------------------
__global__ void combine_kernel(float* __restrict__ out) {
    int t = blockIdx.x;
    int i0 = 2 * t, i1 = 2 * t + 1;
    int e0 = g_item_e[i0], e1 = g_item_e[i1];
    int p0 = g_item_pos[i0], p1 = g_item_pos[i1];
    float w0 = (p0 < CAP) ? g_item_w[i0] : 0.f;
    float w1 = (p1 < CAP) ? g_item_w[i1] : 0.f;
    if (p0 >= CAP) p0 = CAP - 1;
    if (p1 >= CAP) p1 = CAP - 1;
    const float4* s0 = (const float4*)(g_oute + ((size_t)e0 * CAP + p0) * DM);
    const float4* s1 = (const float4*)(g_oute + ((size_t)e1 * CAP + p1) * DM);
    float4* dst = (float4*)(out + (size_t)t * DM);
    for (int j = threadIdx.x; j < DM/4; j += blockDim.x) {
        float4 a = s0[j], b = s1[j];
        float4 r;
        r.x = w0 * a.x + w1 * b.x;
        r.y = w0 * a.y + w1 * b.y;
        r.z = w0 * a.z + w1 * b.z;
        r.w = w0 * a.w + w1 * b.w;
        dst[j] = r;
    }
}

// ---------------- launcher --------------------------
extern "C" void kernel_launch(void* const* d_in, const int* in_sizes, int n_in,
                              void* d_out, int out_size) {
    const float* x  = (const float*)d_in[0];
    const float* gw = (const float*)d_in[1];
    const float* w1 = (const float*)d_in[2];
    const float* b1 = (const float*)d_in[3];
    const float* w2 = (const float*)d_in[4];
    const float* b2 = (const float*)d_in[5];
    float* out = (float*)d_out;

    void *pbuf, *ph, *poute;
    cudaGetSymbolAddress(&pbuf,  g_buf);
    cudaGetSymbolAddress(&ph,    g_h);
    cudaGetSymbolAddress(&poute, g_oute);

    cudaFuncSetAttribute(moe_gemm<true,  true >, cudaFuncAttributeMaxDynamicSharedMemorySize, GSMEM);
    cudaFuncSetAttribute(moe_gemm<false, false>, cudaFuncAttributeMaxDynamicSharedMemorySize, GSMEM);

    gating_kernel<<<T_TOKENS, 128>>>(x, gw);
    position_kernel<<<1, 256>>>();
    dispatch_kernel<<<NITEMS, 128>>>(x);

    // h = relu(buf @ w1 + b1): N=DH, K=DM
    moe_gemm<true,  true ><<<dim3(DH/128, CAP/128, NEXP), 128, GSMEM>>>(
        (const float*)pbuf, w1, b1, (float*)ph, DH, DM);
    // oute = h @ w2 + b2: N=DM, K=DH
    moe_gemm<false, false><<<dim3(DM/128, CAP/128, NEXP), 128, GSMEM>>>(
        (const float*)ph, w2, b2, (float*)poute, DM, DH);

    combine_kernel<<<T_TOKENS, 128>>>(out);
}